// round 10
// baseline (speedup 1.0000x reference)
#include <cuda_runtime.h>
#include <cstdint>

#define BATCH 8
#define SEQ   1024
#define DMODEL 512
#define NHEAD 8
#define HDIM  64

#define TCPAD 68
#define TC_SMEM_BYTES (2 * 128 * TCPAD * 4)

// pipelined AV kernel
#define AVSTR_A 36
#define AVSTR_B 68
#define AV_A_WORDS (64 * AVSTR_A)
#define AV_B_WORDS (32 * AVSTR_B)
#define AV_STAGE   (AV_A_WORDS + AV_B_WORDS)
#define AV_SMEM_BYTES (2 * AV_STAGE * 4)

static __device__ float g_qu [(size_t)BATCH*NHEAD*SEQ*HDIM];
static __device__ float g_qvb[(size_t)BATCH*NHEAD*SEQ*HDIM];
static __device__ float g_kh [(size_t)BATCH*NHEAD*SEQ*HDIM];
static __device__ float g_vh [(size_t)BATCH*NHEAD*SEQ*HDIM];
static __device__ float g_ph [(size_t)BATCH*NHEAD*SEQ*HDIM];
static __device__ float g_ctx[(size_t)BATCH*SEQ*DMODEL];
static __device__ float g_pos[(size_t)BATCH*NHEAD*SEQ*SEQ];
static __device__ uint32_t g_mbits[(size_t)BATCH*SEQ*(SEQ/32)];   // bitpacked mask
static __device__ float g_psum[(size_t)BATCH*NHEAD*SEQ*8];        // row partial sums

__device__ __forceinline__ uint32_t f2tf32(float x) {
    uint32_t t;
    asm("cvt.rna.tf32.f32 %0, %1;" : "=r"(t) : "f"(x));
    return t;
}

__device__ __forceinline__ void mma_tf32(float c[4], const uint32_t a[4], const uint32_t b[2]) {
    asm volatile(
        "mma.sync.aligned.m16n8k8.row.col.f32.tf32.tf32.f32 "
        "{%0,%1,%2,%3}, {%4,%5,%6,%7}, {%8,%9}, {%0,%1,%2,%3};"
        : "+f"(c[0]), "+f"(c[1]), "+f"(c[2]), "+f"(c[3])
        : "r"(a[0]), "r"(a[1]), "r"(a[2]), "r"(a[3]), "r"(b[0]), "r"(b[1]));
}

__device__ __forceinline__ void cp_async16(uint32_t saddr, const void* gptr) {
    asm volatile("cp.async.cg.shared.global [%0], [%1], 16;" :: "r"(saddr), "l"(gptr));
}
__device__ __forceinline__ void cp_commit() { asm volatile("cp.async.commit_group;"); }
template <int N>
__device__ __forceinline__ void cp_wait() { asm volatile("cp.async.wait_group %0;" :: "n"(N)); }

// ---------------------------------------------------------------------------
// Bitpack int32 mask -> 1 bit per element. 262144 words total.
// ---------------------------------------------------------------------------
__global__ __launch_bounds__(256)
void k_maskpack(const int* __restrict__ M, uint32_t* __restrict__ bits)
{
    const int lane = threadIdx.x & 31;
    const size_t gwarp = ((size_t)blockIdx.x * 256 + threadIdx.x) >> 5;  // 8192 warps
    const size_t nwarps = (size_t)gridDim.x * 8;
#pragma unroll
    for (int it = 0; it < 32; it++) {
        size_t w = gwarp + (size_t)it * nwarps;
        uint32_t bal = __ballot_sync(0xffffffffu, M[w * 32 + lane] != 0);
        if (lane == 0) bits[w] = bal;
    }
}

// ---------------------------------------------------------------------------
// TF32 NT projection GEMM: Y = X W^T (+ bias); head-major scatter; dual out opt.
// ---------------------------------------------------------------------------
__global__ __launch_bounds__(256)
void k_proj_tc(const float* __restrict__ X, const float* __restrict__ W,
               const float* __restrict__ bias,
               float* __restrict__ O1, const float* __restrict__ add1,
               float* __restrict__ O2, const float* __restrict__ add2)
{
    extern __shared__ uint32_t sm[];
    uint32_t* As = sm;
    uint32_t* Bs = sm + 128 * TCPAD;

    const int tid = threadIdx.x;
    const int m0 = blockIdx.y * 128;
    const int n0 = blockIdx.x * 128;
    const int lane = tid & 31, warp = tid >> 5;
    const int wm = (warp & 1) * 64, wn = (warp >> 1) * 32;
    const int grp = lane >> 2, tig = lane & 3;

    const int lrow  = tid >> 4;
    const int lcol4 = (tid & 15) * 4;

    float acc[4][4][4] = {};

    for (int k0 = 0; k0 < DMODEL; k0 += 64) {
#pragma unroll
        for (int i = 0; i < 8; i++) {
            int r = lrow + i * 16;
            float4 a4 = *(const float4*)(X + (size_t)(m0 + r) * DMODEL + k0 + lcol4);
            float4 b4 = *(const float4*)(W + (size_t)(n0 + r) * DMODEL + k0 + lcol4);
            *(uint4*)&As[r * TCPAD + lcol4] =
                make_uint4(f2tf32(a4.x), f2tf32(a4.y), f2tf32(a4.z), f2tf32(a4.w));
            *(uint4*)&Bs[r * TCPAD + lcol4] =
                make_uint4(f2tf32(b4.x), f2tf32(b4.y), f2tf32(b4.z), f2tf32(b4.w));
        }
        __syncthreads();

#pragma unroll
        for (int ks = 0; ks < 8; ks++) {
            const int kk = ks * 8;
            uint32_t a[4][4], b[4][2];
#pragma unroll
            for (int tm = 0; tm < 4; tm++) {
                int r = wm + tm * 16 + grp;
                a[tm][0] = As[r * TCPAD + kk + tig];
                a[tm][1] = As[(r + 8) * TCPAD + kk + tig];
                a[tm][2] = As[r * TCPAD + kk + tig + 4];
                a[tm][3] = As[(r + 8) * TCPAD + kk + tig + 4];
            }
#pragma unroll
            for (int tn = 0; tn < 4; tn++) {
                int c = wn + tn * 8 + grp;
                b[tn][0] = Bs[c * TCPAD + kk + tig];
                b[tn][1] = Bs[c * TCPAD + kk + tig + 4];
            }
#pragma unroll
            for (int tm = 0; tm < 4; tm++)
#pragma unroll
                for (int tn = 0; tn < 4; tn++)
                    mma_tf32(acc[tm][tn], a[tm], b[tn]);
        }
        __syncthreads();
    }

#pragma unroll
    for (int tm = 0; tm < 4; tm++) {
#pragma unroll
        for (int tn = 0; tn < 4; tn++) {
            int j = n0 + wn + tn * 8 + tig * 2;
            int hn = j >> 6, hd = j & (HDIM - 1);
            float bj0 = bias ? bias[j] : 0.0f;
            float bj1 = bias ? bias[j + 1] : 0.0f;
#pragma unroll
            for (int half = 0; half < 2; half++) {
                int m = m0 + wm + tm * 16 + grp + half * 8;
                int bb = m >> 10, s = m & (SEQ - 1);
                float v0 = acc[tm][tn][half * 2 + 0] + bj0;
                float v1 = acc[tm][tn][half * 2 + 1] + bj1;
                size_t off = (((size_t)bb * NHEAD + hn) * SEQ + s) * HDIM + hd;
                if (add1) {
                    *(float2*)&O1[off] = make_float2(v0 + add1[j], v1 + add1[j + 1]);
                } else {
                    *(float2*)&O1[off] = make_float2(v0, v1);
                }
                if (O2) {
                    *(float2*)&O2[off] = make_float2(v0 + add2[j], v1 + add2[j + 1]);
                }
            }
        }
    }
}

// ---------------------------------------------------------------------------
// TF32 pos score GEMM (NT, K=64): Pos[z][q][k] = qvb[z][q] . ph[z][k]
// ---------------------------------------------------------------------------
__global__ __launch_bounds__(256)
void k_pos_tc(const float* __restrict__ Aall, const float* __restrict__ Ball,
              float* __restrict__ Call)
{
    extern __shared__ uint32_t sm[];
    uint32_t* As = sm;
    uint32_t* Bs = sm + 128 * TCPAD;

    const int z = blockIdx.z;
    const float* X = Aall + (size_t)z * SEQ * HDIM;
    const float* W = Ball + (size_t)z * SEQ * HDIM;
    float* C = Call + (size_t)z * SEQ * SEQ;

    const int tid = threadIdx.x;
    const int m0 = blockIdx.y * 128;
    const int n0 = blockIdx.x * 128;
    const int lane = tid & 31, warp = tid >> 5;
    const int wm = (warp & 1) * 64, wn = (warp >> 1) * 32;
    const int grp = lane >> 2, tig = lane & 3;

    const int lrow  = tid >> 4;
    const int lcol4 = (tid & 15) * 4;

#pragma unroll
    for (int i = 0; i < 8; i++) {
        int r = lrow + i * 16;
        float4 a4 = *(const float4*)(X + (size_t)(m0 + r) * HDIM + lcol4);
        float4 b4 = *(const float4*)(W + (size_t)(n0 + r) * HDIM + lcol4);
        *(uint4*)&As[r * TCPAD + lcol4] =
            make_uint4(f2tf32(a4.x), f2tf32(a4.y), f2tf32(a4.z), f2tf32(a4.w));
        *(uint4*)&Bs[r * TCPAD + lcol4] =
            make_uint4(f2tf32(b4.x), f2tf32(b4.y), f2tf32(b4.z), f2tf32(b4.w));
    }
    __syncthreads();

    float acc[4][4][4] = {};
#pragma unroll
    for (int ks = 0; ks < 8; ks++) {
        const int kk = ks * 8;
        uint32_t a[4][4], b[4][2];
#pragma unroll
        for (int tm = 0; tm < 4; tm++) {
            int r = wm + tm * 16 + grp;
            a[tm][0] = As[r * TCPAD + kk + tig];
            a[tm][1] = As[(r + 8) * TCPAD + kk + tig];
            a[tm][2] = As[r * TCPAD + kk + tig + 4];
            a[tm][3] = As[(r + 8) * TCPAD + kk + tig + 4];
        }
#pragma unroll
        for (int tn = 0; tn < 4; tn++) {
            int c = wn + tn * 8 + grp;
            b[tn][0] = Bs[c * TCPAD + kk + tig];
            b[tn][1] = Bs[c * TCPAD + kk + tig + 4];
        }
#pragma unroll
        for (int tm = 0; tm < 4; tm++)
#pragma unroll
            for (int tn = 0; tn < 4; tn++)
                mma_tf32(acc[tm][tn], a[tm], b[tn]);
    }

#pragma unroll
    for (int tm = 0; tm < 4; tm++) {
#pragma unroll
        for (int tn = 0; tn < 4; tn++) {
            int col = n0 + wn + tn * 8 + tig * 2;
#pragma unroll
            for (int half = 0; half < 2; half++) {
                int row = m0 + wm + tm * 16 + grp + half * 8;
                *(float2*)&C[(size_t)row * SEQ + col] =
                    make_float2(acc[tm][tn][half * 2 + 0], acc[tm][tn][half * 2 + 1]);
            }
        }
    }
}

// ---------------------------------------------------------------------------
// Fused content GEMM + relative shift + mask + exp + row partial sums.
// Writes UNNORMALIZED exp scores to Attn; per-row partials to Psum.
// shift[q,k] = pos[q, S-1-q+k] (k<=q); 0 (k==q+1); pos[q+1, k-q-2] (k>q+1)
// ---------------------------------------------------------------------------
__global__ __launch_bounds__(256)
void k_scores_fused(const float* __restrict__ Aall, const float* __restrict__ Ball,
                    const float* __restrict__ Pos, const uint32_t* __restrict__ Mbits,
                    float* __restrict__ Attn, float* __restrict__ Psum)
{
    extern __shared__ uint32_t sm[];
    uint32_t* As = sm;
    uint32_t* Bs = sm + 128 * TCPAD;

    const int z = blockIdx.z;
    const int b = z >> 3;
    const float* X = Aall + (size_t)z * SEQ * HDIM;   // qu
    const float* W = Ball + (size_t)z * SEQ * HDIM;   // kh
    const float* Pz = Pos + (size_t)z * SEQ * SEQ;
    float* C = Attn + (size_t)z * SEQ * SEQ;

    const int tid = threadIdx.x;
    const int m0 = blockIdx.y * 128;   // q tile
    const int n0 = blockIdx.x * 128;   // k tile
    const int kb = blockIdx.x;         // partial-sum slot
    const int lane = tid & 31, warp = tid >> 5;
    const int wm = (warp & 1) * 64, wn = (warp >> 1) * 32;
    const int grp = lane >> 2, tig = lane & 3;

    const int lrow  = tid >> 4;
    const int lcol4 = (tid & 15) * 4;

#pragma unroll
    for (int i = 0; i < 8; i++) {
        int r = lrow + i * 16;
        float4 a4 = *(const float4*)(X + (size_t)(m0 + r) * HDIM + lcol4);
        float4 b4 = *(const float4*)(W + (size_t)(n0 + r) * HDIM + lcol4);
        *(uint4*)&As[r * TCPAD + lcol4] =
            make_uint4(f2tf32(a4.x), f2tf32(a4.y), f2tf32(a4.z), f2tf32(a4.w));
        *(uint4*)&Bs[r * TCPAD + lcol4] =
            make_uint4(f2tf32(b4.x), f2tf32(b4.y), f2tf32(b4.z), f2tf32(b4.w));
    }
    __syncthreads();

    float acc[4][4][4] = {};
#pragma unroll
    for (int ks = 0; ks < 8; ks++) {
        const int kk = ks * 8;
        uint32_t a[4][4], bb[4][2];
#pragma unroll
        for (int tm = 0; tm < 4; tm++) {
            int r = wm + tm * 16 + grp;
            a[tm][0] = As[r * TCPAD + kk + tig];
            a[tm][1] = As[(r + 8) * TCPAD + kk + tig];
            a[tm][2] = As[r * TCPAD + kk + tig + 4];
            a[tm][3] = As[(r + 8) * TCPAD + kk + tig + 4];
        }
#pragma unroll
        for (int tn = 0; tn < 4; tn++) {
            int c = wn + tn * 8 + grp;
            bb[tn][0] = Bs[c * TCPAD + kk + tig];
            bb[tn][1] = Bs[c * TCPAD + kk + tig + 4];
        }
#pragma unroll
        for (int tm = 0; tm < 4; tm++)
#pragma unroll
            for (int tn = 0; tn < 4; tn++)
                mma_tf32(acc[tm][tn], a[tm], bb[tn]);
    }
    __syncthreads();   // smem now reused for row partials

    float* rowpart = (float*)sm;                  // [128][16]
    const int colthread = (warp >> 1) * 4 + tig;  // 0..15
    const float scale = 0.04419417382415922f;     // 1/sqrt(512)

#pragma unroll
    for (int tm = 0; tm < 4; tm++) {
#pragma unroll
        for (int half = 0; half < 2; half++) {
            const int rl = wm + tm * 16 + grp + half * 8;   // local q row
            const int qrow = m0 + rl;
            const float* P0 = Pz + (size_t)qrow * SEQ;
            const float* P1 = P0 + SEQ;   // only dereferenced when k > qrow+1 (then qrow<1023)
            const uint32_t* mrow = Mbits + ((size_t)b * SEQ + qrow) * (SEQ / 32);
            float rsum = 0.0f;
#pragma unroll
            for (int tn = 0; tn < 4; tn++) {
                const int kc = n0 + wn + tn * 8 + tig * 2;
                float2 ev;
#pragma unroll
                for (int j = 0; j < 2; j++) {
                    int kcol = kc + j;
                    float c = acc[tm][tn][half * 2 + j];
                    float p;
                    if (kcol <= qrow)           p = P0[SEQ - 1 - qrow + kcol];
                    else if (kcol == qrow + 1)  p = 0.0f;
                    else                        p = P1[kcol - qrow - 2];
                    bool msk = (mrow[kcol >> 5] >> (kcol & 31)) & 1u;
                    float e = msk ? 0.0f : __expf((c + p) * scale);
                    rsum += e;
                    (j == 0 ? ev.x : ev.y) = e;
                }
                *(float2*)&C[(size_t)qrow * SEQ + kc] = ev;
            }
            rowpart[rl * 16 + colthread] = rsum;
        }
    }
    __syncthreads();

    if (tid < 128) {
        float s = 0.0f;
#pragma unroll
        for (int i = 0; i < 16; i++) s += rowpart[tid * 16 + i];
        Psum[((size_t)z * SEQ + m0 + tid) * 8 + kb] = s;
    }
}

// ---------------------------------------------------------------------------
// Pipelined TF32 AV GEMM on unnormalized exp attn. Normalizes attn IN PLACE
// (each block exclusively owns its 64 rows of one z) and scales ctx by 1/rowsum.
// ---------------------------------------------------------------------------
__global__ __launch_bounds__(256)
void k_av_tc(const float* __restrict__ Attn, float* __restrict__ AttnW,
             const float* __restrict__ Vall, const float* __restrict__ Psum,
             float* __restrict__ Ctx)
{
    extern __shared__ float smf[];
    __shared__ float invrow[64];

    const int z = blockIdx.z;
    const int b = z >> 3, n = z & 7;
    const float* Ab = Attn + (size_t)z * SEQ * SEQ;
    float* AbW = AttnW + (size_t)z * SEQ * SEQ;
    const float* Bb = Vall + (size_t)z * SEQ * HDIM;

    const int tid = threadIdx.x;
    const int m0 = blockIdx.y * 64;
    const int lane = tid & 31, warp = tid >> 5;
    const int wm = (warp & 3) * 16, wn = (warp >> 2) * 32;
    const int grp = lane >> 2, tig = lane & 3;

    if (tid < 64) {
        const float* ps = Psum + ((size_t)z * SEQ + m0 + tid) * 8;
        float s = ps[0] + ps[1] + ps[2] + ps[3] + ps[4] + ps[5] + ps[6] + ps[7];
        invrow[tid] = 1.0f / s;
    }

    const int arow = tid >> 2, acol = (tid & 3) * 8;
    const int brow = tid >> 3, bcol = (tid & 7) * 8;

    const uint32_t s0 = (uint32_t)__cvta_generic_to_shared(smf);
    const uint32_t sA = s0 + (arow * AVSTR_A + acol) * 4;
    const uint32_t sB = s0 + (AV_A_WORDS + brow * AVSTR_B + bcol) * 4;
    const float* Agp = Ab + (size_t)(m0 + arow) * SEQ + acol;
    const float* Bgp = Bb + (size_t)brow * HDIM + bcol;

    float acc[4][4] = {};

    const int NK = SEQ / 32;

    cp_async16(sA,      Agp);
    cp_async16(sA + 16, Agp + 4);
    cp_async16(sB,      Bgp);
    cp_async16(sB + 16, Bgp + 4);
    cp_commit();

    for (int t = 0; t < NK; t++) {
        const int cur = t & 1;
        if (t + 1 < NK) {
            const uint32_t off = (uint32_t)((cur ^ 1) * AV_STAGE * 4);
            const int k0 = (t + 1) * 32;
            cp_async16(sA + off,      Agp + k0);
            cp_async16(sA + off + 16, Agp + k0 + 4);
            cp_async16(sB + off,      Bgp + (size_t)k0 * HDIM);
            cp_async16(sB + off + 16, Bgp + (size_t)k0 * HDIM + 4);
            cp_commit();
            cp_wait<1>();
        } else {
            cp_wait<0>();
        }
        __syncthreads();

        const float* As = smf + cur * AV_STAGE;
        const float* Bs = As + AV_A_WORDS;

        // write normalized attn for this tile (exclusive row ownership)
        {
            const float inv = invrow[arow];
            const float* src = As + arow * AVSTR_A + acol;
            float* dst = AbW + (size_t)(m0 + arow) * SEQ + t * 32 + acol;
            float4 v0 = make_float4(src[0] * inv, src[1] * inv, src[2] * inv, src[3] * inv);
            float4 v1 = make_float4(src[4] * inv, src[5] * inv, src[6] * inv, src[7] * inv);
            *(float4*)dst = v0;
            *(float4*)(dst + 4) = v1;
        }

#pragma unroll
        for (int ks = 0; ks < 4; ks++) {
            const int kk = ks * 8;
            uint32_t a[4], bfr[4][2];
            {
                int r = wm + grp;
                a[0] = f2tf32(As[r * AVSTR_A + kk + tig]);
                a[1] = f2tf32(As[(r + 8) * AVSTR_A + kk + tig]);
                a[2] = f2tf32(As[r * AVSTR_A + kk + tig + 4]);
                a[3] = f2tf32(As[(r + 8) * AVSTR_A + kk + tig + 4]);
            }
#pragma unroll
            for (int tn = 0; tn < 4; tn++) {
                int c = wn + tn * 8 + grp;
                bfr[tn][0] = f2tf32(Bs[(kk + tig) * AVSTR_B + c]);
                bfr[tn][1] = f2tf32(Bs[(kk + tig + 4) * AVSTR_B + c]);
            }
#pragma unroll
            for (int tn = 0; tn < 4; tn++)
                mma_tf32(acc[tn], a, bfr[tn]);
        }
        __syncthreads();
    }

    const float inv0 = invrow[wm + grp];
    const float inv1 = invrow[wm + grp + 8];
#pragma unroll
    for (int tn = 0; tn < 4; tn++) {
        int d = wn + tn * 8 + tig * 2;
#pragma unroll
        for (int half = 0; half < 2; half++) {
            int qrow = m0 + wm + grp + half * 8;
            float inv = half ? inv1 : inv0;
            *(float2*)&Ctx[((size_t)b * SEQ + qrow) * DMODEL + n * HDIM + d] =
                make_float2(acc[tn][half * 2 + 0] * inv, acc[tn][half * 2 + 1] * inv);
        }
    }
}

// ---------------------------------------------------------------------------
// TF32 output NT GEMM: Out[m,j] = sum_d Ctx[m,d]*Wout[j,d] + bout[j]
// ---------------------------------------------------------------------------
__global__ __launch_bounds__(256)
void k_out_tc(const float* __restrict__ X, const float* __restrict__ W,
              const float* __restrict__ bias, float* __restrict__ Out)
{
    extern __shared__ uint32_t sm[];
    uint32_t* As = sm;
    uint32_t* Bs = sm + 128 * TCPAD;

    const int tid = threadIdx.x;
    const int m0 = blockIdx.y * 128;
    const int n0 = blockIdx.x * 128;
    const int lane = tid & 31, warp = tid >> 5;
    const int wm = (warp & 1) * 64, wn = (warp >> 1) * 32;
    const int grp = lane >> 2, tig = lane & 3;

    const int lrow  = tid >> 4;
    const int lcol4 = (tid & 15) * 4;

    float acc[4][4][4] = {};

    for (int k0 = 0; k0 < DMODEL; k0 += 64) {
#pragma unroll
        for (int i = 0; i < 8; i++) {
            int r = lrow + i * 16;
            float4 a4 = *(const float4*)(X + (size_t)(m0 + r) * DMODEL + k0 + lcol4);
            float4 b4 = *(const float4*)(W + (size_t)(n0 + r) * DMODEL + k0 + lcol4);
            *(uint4*)&As[r * TCPAD + lcol4] =
                make_uint4(f2tf32(a4.x), f2tf32(a4.y), f2tf32(a4.z), f2tf32(a4.w));
            *(uint4*)&Bs[r * TCPAD + lcol4] =
                make_uint4(f2tf32(b4.x), f2tf32(b4.y), f2tf32(b4.z), f2tf32(b4.w));
        }
        __syncthreads();

#pragma unroll
        for (int ks = 0; ks < 8; ks++) {
            const int kk = ks * 8;
            uint32_t a[4][4], b[4][2];
#pragma unroll
            for (int tm = 0; tm < 4; tm++) {
                int r = wm + tm * 16 + grp;
                a[tm][0] = As[r * TCPAD + kk + tig];
                a[tm][1] = As[(r + 8) * TCPAD + kk + tig];
                a[tm][2] = As[r * TCPAD + kk + tig + 4];
                a[tm][3] = As[(r + 8) * TCPAD + kk + tig + 4];
            }
#pragma unroll
            for (int tn = 0; tn < 4; tn++) {
                int c = wn + tn * 8 + grp;
                b[tn][0] = Bs[c * TCPAD + kk + tig];
                b[tn][1] = Bs[c * TCPAD + kk + tig + 4];
            }
#pragma unroll
            for (int tm = 0; tm < 4; tm++)
#pragma unroll
                for (int tn = 0; tn < 4; tn++)
                    mma_tf32(acc[tm][tn], a[tm], b[tn]);
        }
        __syncthreads();
    }

#pragma unroll
    for (int tm = 0; tm < 4; tm++) {
#pragma unroll
        for (int tn = 0; tn < 4; tn++) {
            int j = n0 + wn + tn * 8 + tig * 2;
            float bj0 = bias[j], bj1 = bias[j + 1];
#pragma unroll
            for (int half = 0; half < 2; half++) {
                int m = m0 + wm + tm * 16 + grp + half * 8;
                *(float2*)&Out[(size_t)m * DMODEL + j] =
                    make_float2(acc[tm][tn][half * 2 + 0] + bj0,
                                acc[tm][tn][half * 2 + 1] + bj1);
            }
        }
    }
}

extern "C" void kernel_launch(void* const* d_in, const int* in_sizes, int n_in,
                              void* d_out, int out_size)
{
    const float* q       = (const float*)d_in[0];
    const float* k       = (const float*)d_in[1];
    const float* v       = (const float*)d_in[2];
    const float* pos_emb = (const float*)d_in[3];
    const int*   mask    = (const int*)d_in[4];   // bool -> int32 in harness
    const float* Wq   = (const float*)d_in[5];
    const float* bq   = (const float*)d_in[6];
    const float* Wk   = (const float*)d_in[7];
    const float* bk   = (const float*)d_in[8];
    const float* Wv   = (const float*)d_in[9];
    const float* bv   = (const float*)d_in[10];
    const float* Wpos = (const float*)d_in[11];
    const float* Wout = (const float*)d_in[12];
    const float* bout = (const float*)d_in[13];
    const float* u      = (const float*)d_in[14];
    const float* v_bias = (const float*)d_in[15];

    float* out = (float*)d_out;
    float* out_ctx  = out;                                  // [8,1024,512]
    float* out_attn = out + (size_t)BATCH * SEQ * DMODEL;   // [8,8,1024,1024]

    static float *p_qu = nullptr, *p_qvb, *p_kh, *p_vh, *p_ph, *p_ctx, *p_pos, *p_psum;
    static uint32_t* p_mbits;
    if (!p_qu) {
        cudaGetSymbolAddress((void**)&p_qu,  g_qu);
        cudaGetSymbolAddress((void**)&p_qvb, g_qvb);
        cudaGetSymbolAddress((void**)&p_kh,  g_kh);
        cudaGetSymbolAddress((void**)&p_vh,  g_vh);
        cudaGetSymbolAddress((void**)&p_ph,  g_ph);
        cudaGetSymbolAddress((void**)&p_ctx, g_ctx);
        cudaGetSymbolAddress((void**)&p_pos, g_pos);
        cudaGetSymbolAddress((void**)&p_psum, g_psum);
        cudaGetSymbolAddress((void**)&p_mbits, g_mbits);
        cudaFuncSetAttribute(k_proj_tc,      cudaFuncAttributeMaxDynamicSharedMemorySize, TC_SMEM_BYTES);
        cudaFuncSetAttribute(k_pos_tc,       cudaFuncAttributeMaxDynamicSharedMemorySize, TC_SMEM_BYTES);
        cudaFuncSetAttribute(k_scores_fused, cudaFuncAttributeMaxDynamicSharedMemorySize, TC_SMEM_BYTES);
        cudaFuncSetAttribute(k_av_tc,        cudaFuncAttributeMaxDynamicSharedMemorySize, AV_SMEM_BYTES);
        cudaFuncSetAttribute(k_out_tc,       cudaFuncAttributeMaxDynamicSharedMemorySize, TC_SMEM_BYTES);
    }

    // mask bitpack (independent of projections)
    k_maskpack<<<1024, 256>>>(mask, p_mbits);

    // tf32 tensor projections
    dim3 gptc(DMODEL / 128, (BATCH * SEQ) / 128);   // (4, 64)
    k_proj_tc<<<gptc, 256, TC_SMEM_BYTES>>>(q,       Wq,   bq, p_qu, u, p_qvb, v_bias);
    k_proj_tc<<<gptc, 256, TC_SMEM_BYTES>>>(k,       Wk,   bk, p_kh, nullptr, nullptr, nullptr);
    k_proj_tc<<<gptc, 256, TC_SMEM_BYTES>>>(pos_emb, Wpos, nullptr, p_ph, nullptr, nullptr, nullptr);
    k_proj_tc<<<gptc, 256, TC_SMEM_BYTES>>>(v,       Wv,   bv, p_vh, nullptr, nullptr, nullptr);

    // pos scores -> scratch
    dim3 gs(SEQ / 128, SEQ / 128, BATCH * NHEAD);   // (8, 8, 64)
    k_pos_tc<<<gs, 256, TC_SMEM_BYTES>>>(p_qvb, p_ph, p_pos);

    // fused content GEMM + shift + mask + exp + row partials
    k_scores_fused<<<gs, 256, TC_SMEM_BYTES>>>(p_qu, p_kh, p_pos, p_mbits,
                                               out_attn, p_psum);

    // pipelined AV on exp-attn; normalizes attn in place + scales ctx
    dim3 ga(1, SEQ / 64, BATCH * NHEAD);            // (1, 16, 64)
    k_av_tc<<<ga, 256, AV_SMEM_BYTES>>>(out_attn, out_attn, p_vh, p_psum, p_ctx);

    // tf32 output projection
    dim3 go(DMODEL / 128, (BATCH * SEQ) / 128);     // (4, 64)
    k_out_tc<<<go, 256, TC_SMEM_BYTES>>>(p_ctx, Wout, bout, out_ctx);
}

// round 13
// speedup vs baseline: 1.0003x; 1.0003x over previous
#include <cuda_runtime.h>
#include <cstdint>

#define BATCH 8
#define SEQ   1024
#define DMODEL 512
#define NHEAD 8
#define HDIM  64

#define TCPAD 68
#define TC_SMEM_BYTES (2 * 128 * TCPAD * 4)

// pipelined AV kernel
#define AVSTR_A 36
#define AVSTR_B 68
#define AV_A_WORDS (64 * AVSTR_A)
#define AV_B_WORDS (32 * AVSTR_B)
#define AV_STAGE   (AV_A_WORDS + AV_B_WORDS)
#define AV_SMEM_BYTES (2 * AV_STAGE * 4)

static __device__ float g_qu [(size_t)BATCH*NHEAD*SEQ*HDIM];
static __device__ float g_qvb[(size_t)BATCH*NHEAD*SEQ*HDIM];
static __device__ float g_kh [(size_t)BATCH*NHEAD*SEQ*HDIM];
static __device__ float g_vh [(size_t)BATCH*NHEAD*SEQ*HDIM];
static __device__ float g_ph [(size_t)BATCH*NHEAD*SEQ*HDIM];
static __device__ float g_ctx[(size_t)BATCH*SEQ*DMODEL];
static __device__ float g_pos[(size_t)BATCH*NHEAD*SEQ*SEQ];
static __device__ uint32_t g_mbits[(size_t)BATCH*SEQ*(SEQ/32)];   // bitpacked mask
static __device__ float g_psum[(size_t)BATCH*NHEAD*SEQ*8];        // row partial sums

__device__ __forceinline__ uint32_t f2tf32(float x) {
    uint32_t t;
    asm("cvt.rna.tf32.f32 %0, %1;" : "=r"(t) : "f"(x));
    return t;
}

__device__ __forceinline__ void mma_tf32(float c[4], const uint32_t a[4], const uint32_t b[2]) {
    asm volatile(
        "mma.sync.aligned.m16n8k8.row.col.f32.tf32.tf32.f32 "
        "{%0,%1,%2,%3}, {%4,%5,%6,%7}, {%8,%9}, {%0,%1,%2,%3};"
        : "+f"(c[0]), "+f"(c[1]), "+f"(c[2]), "+f"(c[3])
        : "r"(a[0]), "r"(a[1]), "r"(a[2]), "r"(a[3]), "r"(b[0]), "r"(b[1]));
}

__device__ __forceinline__ void cp_async16(uint32_t saddr, const void* gptr) {
    asm volatile("cp.async.cg.shared.global [%0], [%1], 16;" :: "r"(saddr), "l"(gptr));
}
__device__ __forceinline__ void cp_commit() { asm volatile("cp.async.commit_group;"); }
template <int N>
__device__ __forceinline__ void cp_wait() { asm volatile("cp.async.wait_group %0;" :: "n"(N)); }

// ---------------------------------------------------------------------------
// Bitpack int32 mask -> 1 bit per element. 262144 words total.
// ---------------------------------------------------------------------------
__global__ __launch_bounds__(256)
void k_maskpack(const int* __restrict__ M, uint32_t* __restrict__ bits)
{
    const int lane = threadIdx.x & 31;
    const size_t gwarp = ((size_t)blockIdx.x * 256 + threadIdx.x) >> 5;  // 8192 warps
    const size_t nwarps = (size_t)gridDim.x * 8;
#pragma unroll
    for (int it = 0; it < 32; it++) {
        size_t w = gwarp + (size_t)it * nwarps;
        uint32_t bal = __ballot_sync(0xffffffffu, M[w * 32 + lane] != 0);
        if (lane == 0) bits[w] = bal;
    }
}

// ---------------------------------------------------------------------------
// TF32 NT projection GEMM: Y = X W^T (+ bias); head-major scatter; dual out opt.
// ---------------------------------------------------------------------------
__global__ __launch_bounds__(256)
void k_proj_tc(const float* __restrict__ X, const float* __restrict__ W,
               const float* __restrict__ bias,
               float* __restrict__ O1, const float* __restrict__ add1,
               float* __restrict__ O2, const float* __restrict__ add2)
{
    extern __shared__ uint32_t sm[];
    uint32_t* As = sm;
    uint32_t* Bs = sm + 128 * TCPAD;

    const int tid = threadIdx.x;
    const int m0 = blockIdx.y * 128;
    const int n0 = blockIdx.x * 128;
    const int lane = tid & 31, warp = tid >> 5;
    const int wm = (warp & 1) * 64, wn = (warp >> 1) * 32;
    const int grp = lane >> 2, tig = lane & 3;

    const int lrow  = tid >> 4;
    const int lcol4 = (tid & 15) * 4;

    float acc[4][4][4] = {};

    for (int k0 = 0; k0 < DMODEL; k0 += 64) {
#pragma unroll
        for (int i = 0; i < 8; i++) {
            int r = lrow + i * 16;
            float4 a4 = *(const float4*)(X + (size_t)(m0 + r) * DMODEL + k0 + lcol4);
            float4 b4 = *(const float4*)(W + (size_t)(n0 + r) * DMODEL + k0 + lcol4);
            *(uint4*)&As[r * TCPAD + lcol4] =
                make_uint4(f2tf32(a4.x), f2tf32(a4.y), f2tf32(a4.z), f2tf32(a4.w));
            *(uint4*)&Bs[r * TCPAD + lcol4] =
                make_uint4(f2tf32(b4.x), f2tf32(b4.y), f2tf32(b4.z), f2tf32(b4.w));
        }
        __syncthreads();

#pragma unroll
        for (int ks = 0; ks < 8; ks++) {
            const int kk = ks * 8;
            uint32_t a[4][4], b[4][2];
#pragma unroll
            for (int tm = 0; tm < 4; tm++) {
                int r = wm + tm * 16 + grp;
                a[tm][0] = As[r * TCPAD + kk + tig];
                a[tm][1] = As[(r + 8) * TCPAD + kk + tig];
                a[tm][2] = As[r * TCPAD + kk + tig + 4];
                a[tm][3] = As[(r + 8) * TCPAD + kk + tig + 4];
            }
#pragma unroll
            for (int tn = 0; tn < 4; tn++) {
                int c = wn + tn * 8 + grp;
                b[tn][0] = Bs[c * TCPAD + kk + tig];
                b[tn][1] = Bs[c * TCPAD + kk + tig + 4];
            }
#pragma unroll
            for (int tm = 0; tm < 4; tm++)
#pragma unroll
                for (int tn = 0; tn < 4; tn++)
                    mma_tf32(acc[tm][tn], a[tm], b[tn]);
        }
        __syncthreads();
    }

#pragma unroll
    for (int tm = 0; tm < 4; tm++) {
#pragma unroll
        for (int tn = 0; tn < 4; tn++) {
            int j = n0 + wn + tn * 8 + tig * 2;
            int hn = j >> 6, hd = j & (HDIM - 1);
            float bj0 = bias ? bias[j] : 0.0f;
            float bj1 = bias ? bias[j + 1] : 0.0f;
#pragma unroll
            for (int half = 0; half < 2; half++) {
                int m = m0 + wm + tm * 16 + grp + half * 8;
                int bb = m >> 10, s = m & (SEQ - 1);
                float v0 = acc[tm][tn][half * 2 + 0] + bj0;
                float v1 = acc[tm][tn][half * 2 + 1] + bj1;
                size_t off = (((size_t)bb * NHEAD + hn) * SEQ + s) * HDIM + hd;
                if (add1) {
                    *(float2*)&O1[off] = make_float2(v0 + add1[j], v1 + add1[j + 1]);
                } else {
                    *(float2*)&O1[off] = make_float2(v0, v1);
                }
                if (O2) {
                    *(float2*)&O2[off] = make_float2(v0 + add2[j], v1 + add2[j + 1]);
                }
            }
        }
    }
}

// ---------------------------------------------------------------------------
// TF32 pos score GEMM (NT, K=64): Pos[z][q][k] = qvb[z][q] . ph[z][k]
// ---------------------------------------------------------------------------
__global__ __launch_bounds__(256)
void k_pos_tc(const float* __restrict__ Aall, const float* __restrict__ Ball,
              float* __restrict__ Call)
{
    extern __shared__ uint32_t sm[];
    uint32_t* As = sm;
    uint32_t* Bs = sm + 128 * TCPAD;

    const int z = blockIdx.z;
    const float* X = Aall + (size_t)z * SEQ * HDIM;
    const float* W = Ball + (size_t)z * SEQ * HDIM;
    float* C = Call + (size_t)z * SEQ * SEQ;

    const int tid = threadIdx.x;
    const int m0 = blockIdx.y * 128;
    const int n0 = blockIdx.x * 128;
    const int lane = tid & 31, warp = tid >> 5;
    const int wm = (warp & 1) * 64, wn = (warp >> 1) * 32;
    const int grp = lane >> 2, tig = lane & 3;

    const int lrow  = tid >> 4;
    const int lcol4 = (tid & 15) * 4;

#pragma unroll
    for (int i = 0; i < 8; i++) {
        int r = lrow + i * 16;
        float4 a4 = *(const float4*)(X + (size_t)(m0 + r) * HDIM + lcol4);
        float4 b4 = *(const float4*)(W + (size_t)(n0 + r) * HDIM + lcol4);
        *(uint4*)&As[r * TCPAD + lcol4] =
            make_uint4(f2tf32(a4.x), f2tf32(a4.y), f2tf32(a4.z), f2tf32(a4.w));
        *(uint4*)&Bs[r * TCPAD + lcol4] =
            make_uint4(f2tf32(b4.x), f2tf32(b4.y), f2tf32(b4.z), f2tf32(b4.w));
    }
    __syncthreads();

    float acc[4][4][4] = {};
#pragma unroll
    for (int ks = 0; ks < 8; ks++) {
        const int kk = ks * 8;
        uint32_t a[4][4], b[4][2];
#pragma unroll
        for (int tm = 0; tm < 4; tm++) {
            int r = wm + tm * 16 + grp;
            a[tm][0] = As[r * TCPAD + kk + tig];
            a[tm][1] = As[(r + 8) * TCPAD + kk + tig];
            a[tm][2] = As[r * TCPAD + kk + tig + 4];
            a[tm][3] = As[(r + 8) * TCPAD + kk + tig + 4];
        }
#pragma unroll
        for (int tn = 0; tn < 4; tn++) {
            int c = wn + tn * 8 + grp;
            b[tn][0] = Bs[c * TCPAD + kk + tig];
            b[tn][1] = Bs[c * TCPAD + kk + tig + 4];
        }
#pragma unroll
        for (int tm = 0; tm < 4; tm++)
#pragma unroll
            for (int tn = 0; tn < 4; tn++)
                mma_tf32(acc[tm][tn], a[tm], b[tn]);
    }

#pragma unroll
    for (int tm = 0; tm < 4; tm++) {
#pragma unroll
        for (int tn = 0; tn < 4; tn++) {
            int col = n0 + wn + tn * 8 + tig * 2;
#pragma unroll
            for (int half = 0; half < 2; half++) {
                int row = m0 + wm + tm * 16 + grp + half * 8;
                *(float2*)&C[(size_t)row * SEQ + col] =
                    make_float2(acc[tm][tn][half * 2 + 0], acc[tm][tn][half * 2 + 1]);
            }
        }
    }
}

// ---------------------------------------------------------------------------
// Fused content GEMM + relative shift + mask + exp + row partial sums.
// Writes UNNORMALIZED exp scores to Attn; per-row partials to Psum.
// shift[q,k] = pos[q, S-1-q+k] (k<=q); 0 (k==q+1); pos[q+1, k-q-2] (k>q+1)
// ---------------------------------------------------------------------------
__global__ __launch_bounds__(256)
void k_scores_fused(const float* __restrict__ Aall, const float* __restrict__ Ball,
                    const float* __restrict__ Pos, const uint32_t* __restrict__ Mbits,
                    float* __restrict__ Attn, float* __restrict__ Psum)
{
    extern __shared__ uint32_t sm[];
    uint32_t* As = sm;
    uint32_t* Bs = sm + 128 * TCPAD;

    const int z = blockIdx.z;
    const int b = z >> 3;
    const float* X = Aall + (size_t)z * SEQ * HDIM;   // qu
    const float* W = Ball + (size_t)z * SEQ * HDIM;   // kh
    const float* Pz = Pos + (size_t)z * SEQ * SEQ;
    float* C = Attn + (size_t)z * SEQ * SEQ;

    const int tid = threadIdx.x;
    const int m0 = blockIdx.y * 128;   // q tile
    const int n0 = blockIdx.x * 128;   // k tile
    const int kb = blockIdx.x;         // partial-sum slot
    const int lane = tid & 31, warp = tid >> 5;
    const int wm = (warp & 1) * 64, wn = (warp >> 1) * 32;
    const int grp = lane >> 2, tig = lane & 3;

    const int lrow  = tid >> 4;
    const int lcol4 = (tid & 15) * 4;

#pragma unroll
    for (int i = 0; i < 8; i++) {
        int r = lrow + i * 16;
        float4 a4 = *(const float4*)(X + (size_t)(m0 + r) * HDIM + lcol4);
        float4 b4 = *(const float4*)(W + (size_t)(n0 + r) * HDIM + lcol4);
        *(uint4*)&As[r * TCPAD + lcol4] =
            make_uint4(f2tf32(a4.x), f2tf32(a4.y), f2tf32(a4.z), f2tf32(a4.w));
        *(uint4*)&Bs[r * TCPAD + lcol4] =
            make_uint4(f2tf32(b4.x), f2tf32(b4.y), f2tf32(b4.z), f2tf32(b4.w));
    }
    __syncthreads();

    float acc[4][4][4] = {};
#pragma unroll
    for (int ks = 0; ks < 8; ks++) {
        const int kk = ks * 8;
        uint32_t a[4][4], bb[4][2];
#pragma unroll
        for (int tm = 0; tm < 4; tm++) {
            int r = wm + tm * 16 + grp;
            a[tm][0] = As[r * TCPAD + kk + tig];
            a[tm][1] = As[(r + 8) * TCPAD + kk + tig];
            a[tm][2] = As[r * TCPAD + kk + tig + 4];
            a[tm][3] = As[(r + 8) * TCPAD + kk + tig + 4];
        }
#pragma unroll
        for (int tn = 0; tn < 4; tn++) {
            int c = wn + tn * 8 + grp;
            bb[tn][0] = Bs[c * TCPAD + kk + tig];
            bb[tn][1] = Bs[c * TCPAD + kk + tig + 4];
        }
#pragma unroll
        for (int tm = 0; tm < 4; tm++)
#pragma unroll
            for (int tn = 0; tn < 4; tn++)
                mma_tf32(acc[tm][tn], a[tm], bb[tn]);
    }
    __syncthreads();   // smem now reused for row partials

    float* rowpart = (float*)sm;                  // [128][16]
    const int colthread = (warp >> 1) * 4 + tig;  // 0..15
    const float scale = 0.04419417382415922f;     // 1/sqrt(512)

#pragma unroll
    for (int tm = 0; tm < 4; tm++) {
#pragma unroll
        for (int half = 0; half < 2; half++) {
            const int rl = wm + tm * 16 + grp + half * 8;   // local q row
            const int qrow = m0 + rl;
            const float* P0 = Pz + (size_t)qrow * SEQ;
            const float* P1 = P0 + SEQ;   // only dereferenced when k > qrow+1 (then qrow<1023)
            const uint32_t* mrow = Mbits + ((size_t)b * SEQ + qrow) * (SEQ / 32);
            float rsum = 0.0f;
#pragma unroll
            for (int tn = 0; tn < 4; tn++) {
                const int kc = n0 + wn + tn * 8 + tig * 2;
                float2 ev;
#pragma unroll
                for (int j = 0; j < 2; j++) {
                    int kcol = kc + j;
                    float c = acc[tm][tn][half * 2 + j];
                    float p;
                    if (kcol <= qrow)           p = P0[SEQ - 1 - qrow + kcol];
                    else if (kcol == qrow + 1)  p = 0.0f;
                    else                        p = P1[kcol - qrow - 2];
                    bool msk = (mrow[kcol >> 5] >> (kcol & 31)) & 1u;
                    float e = msk ? 0.0f : __expf((c + p) * scale);
                    rsum += e;
                    (j == 0 ? ev.x : ev.y) = e;
                }
                *(float2*)&C[(size_t)qrow * SEQ + kc] = ev;
            }
            rowpart[rl * 16 + colthread] = rsum;
        }
    }
    __syncthreads();

    if (tid < 128) {
        float s = 0.0f;
#pragma unroll
        for (int i = 0; i < 16; i++) s += rowpart[tid * 16 + i];
        Psum[((size_t)z * SEQ + m0 + tid) * 8 + kb] = s;
    }
}

// ---------------------------------------------------------------------------
// Pipelined TF32 AV GEMM on unnormalized exp attn. Normalizes attn IN PLACE
// (each block exclusively owns its 64 rows of one z) and scales ctx by 1/rowsum.
// ---------------------------------------------------------------------------
__global__ __launch_bounds__(256)
void k_av_tc(const float* __restrict__ Attn, float* __restrict__ AttnW,
             const float* __restrict__ Vall, const float* __restrict__ Psum,
             float* __restrict__ Ctx)
{
    extern __shared__ float smf[];
    __shared__ float invrow[64];

    const int z = blockIdx.z;
    const int b = z >> 3, n = z & 7;
    const float* Ab = Attn + (size_t)z * SEQ * SEQ;
    float* AbW = AttnW + (size_t)z * SEQ * SEQ;
    const float* Bb = Vall + (size_t)z * SEQ * HDIM;

    const int tid = threadIdx.x;
    const int m0 = blockIdx.y * 64;
    const int lane = tid & 31, warp = tid >> 5;
    const int wm = (warp & 3) * 16, wn = (warp >> 2) * 32;
    const int grp = lane >> 2, tig = lane & 3;

    if (tid < 64) {
        const float* ps = Psum + ((size_t)z * SEQ + m0 + tid) * 8;
        float s = ps[0] + ps[1] + ps[2] + ps[3] + ps[4] + ps[5] + ps[6] + ps[7];
        invrow[tid] = 1.0f / s;
    }

    const int arow = tid >> 2, acol = (tid & 3) * 8;
    const int brow = tid >> 3, bcol = (tid & 7) * 8;

    const uint32_t s0 = (uint32_t)__cvta_generic_to_shared(smf);
    const uint32_t sA = s0 + (arow * AVSTR_A + acol) * 4;
    const uint32_t sB = s0 + (AV_A_WORDS + brow * AVSTR_B + bcol) * 4;
    const float* Agp = Ab + (size_t)(m0 + arow) * SEQ + acol;
    const float* Bgp = Bb + (size_t)brow * HDIM + bcol;

    float acc[4][4] = {};

    const int NK = SEQ / 32;

    cp_async16(sA,      Agp);
    cp_async16(sA + 16, Agp + 4);
    cp_async16(sB,      Bgp);
    cp_async16(sB + 16, Bgp + 4);
    cp_commit();

    for (int t = 0; t < NK; t++) {
        const int cur = t & 1;
        if (t + 1 < NK) {
            const uint32_t off = (uint32_t)((cur ^ 1) * AV_STAGE * 4);
            const int k0 = (t + 1) * 32;
            cp_async16(sA + off,      Agp + k0);
            cp_async16(sA + off + 16, Agp + k0 + 4);
            cp_async16(sB + off,      Bgp + (size_t)k0 * HDIM);
            cp_async16(sB + off + 16, Bgp + (size_t)k0 * HDIM + 4);
            cp_commit();
            cp_wait<1>();
        } else {
            cp_wait<0>();
        }
        __syncthreads();

        const float* As = smf + cur * AV_STAGE;
        const float* Bs = As + AV_A_WORDS;

        // write normalized attn for this tile (exclusive row ownership)
        {
            const float inv = invrow[arow];
            const float* src = As + arow * AVSTR_A + acol;
            float* dst = AbW + (size_t)(m0 + arow) * SEQ + t * 32 + acol;
            float4 v0 = make_float4(src[0] * inv, src[1] * inv, src[2] * inv, src[3] * inv);
            float4 v1 = make_float4(src[4] * inv, src[5] * inv, src[6] * inv, src[7] * inv);
            *(float4*)dst = v0;
            *(float4*)(dst + 4) = v1;
        }

#pragma unroll
        for (int ks = 0; ks < 4; ks++) {
            const int kk = ks * 8;
            uint32_t a[4], bfr[4][2];
            {
                int r = wm + grp;
                a[0] = f2tf32(As[r * AVSTR_A + kk + tig]);
                a[1] = f2tf32(As[(r + 8) * AVSTR_A + kk + tig]);
                a[2] = f2tf32(As[r * AVSTR_A + kk + tig + 4]);
                a[3] = f2tf32(As[(r + 8) * AVSTR_A + kk + tig + 4]);
            }
#pragma unroll
            for (int tn = 0; tn < 4; tn++) {
                int c = wn + tn * 8 + grp;
                bfr[tn][0] = f2tf32(Bs[(kk + tig) * AVSTR_B + c]);
                bfr[tn][1] = f2tf32(Bs[(kk + tig + 4) * AVSTR_B + c]);
            }
#pragma unroll
            for (int tn = 0; tn < 4; tn++)
                mma_tf32(acc[tn], a, bfr[tn]);
        }
        __syncthreads();
    }

    const float inv0 = invrow[wm + grp];
    const float inv1 = invrow[wm + grp + 8];
#pragma unroll
    for (int tn = 0; tn < 4; tn++) {
        int d = wn + tn * 8 + tig * 2;
#pragma unroll
        for (int half = 0; half < 2; half++) {
            int qrow = m0 + wm + grp + half * 8;
            float inv = half ? inv1 : inv0;
            *(float2*)&Ctx[((size_t)b * SEQ + qrow) * DMODEL + n * HDIM + d] =
                make_float2(acc[tn][half * 2 + 0] * inv, acc[tn][half * 2 + 1] * inv);
        }
    }
}

// ---------------------------------------------------------------------------
// TF32 output NT GEMM: Out[m,j] = sum_d Ctx[m,d]*Wout[j,d] + bout[j]
// ---------------------------------------------------------------------------
__global__ __launch_bounds__(256)
void k_out_tc(const float* __restrict__ X, const float* __restrict__ W,
              const float* __restrict__ bias, float* __restrict__ Out)
{
    extern __shared__ uint32_t sm[];
    uint32_t* As = sm;
    uint32_t* Bs = sm + 128 * TCPAD;

    const int tid = threadIdx.x;
    const int m0 = blockIdx.y * 128;
    const int n0 = blockIdx.x * 128;
    const int lane = tid & 31, warp = tid >> 5;
    const int wm = (warp & 1) * 64, wn = (warp >> 1) * 32;
    const int grp = lane >> 2, tig = lane & 3;

    const int lrow  = tid >> 4;
    const int lcol4 = (tid & 15) * 4;

    float acc[4][4][4] = {};

    for (int k0 = 0; k0 < DMODEL; k0 += 64) {
#pragma unroll
        for (int i = 0; i < 8; i++) {
            int r = lrow + i * 16;
            float4 a4 = *(const float4*)(X + (size_t)(m0 + r) * DMODEL + k0 + lcol4);
            float4 b4 = *(const float4*)(W + (size_t)(n0 + r) * DMODEL + k0 + lcol4);
            *(uint4*)&As[r * TCPAD + lcol4] =
                make_uint4(f2tf32(a4.x), f2tf32(a4.y), f2tf32(a4.z), f2tf32(a4.w));
            *(uint4*)&Bs[r * TCPAD + lcol4] =
                make_uint4(f2tf32(b4.x), f2tf32(b4.y), f2tf32(b4.z), f2tf32(b4.w));
        }
        __syncthreads();

#pragma unroll
        for (int ks = 0; ks < 8; ks++) {
            const int kk = ks * 8;
            uint32_t a[4][4], b[4][2];
#pragma unroll
            for (int tm = 0; tm < 4; tm++) {
                int r = wm + tm * 16 + grp;
                a[tm][0] = As[r * TCPAD + kk + tig];
                a[tm][1] = As[(r + 8) * TCPAD + kk + tig];
                a[tm][2] = As[r * TCPAD + kk + tig + 4];
                a[tm][3] = As[(r + 8) * TCPAD + kk + tig + 4];
            }
#pragma unroll
            for (int tn = 0; tn < 4; tn++) {
                int c = wn + tn * 8 + grp;
                b[tn][0] = Bs[c * TCPAD + kk + tig];
                b[tn][1] = Bs[c * TCPAD + kk + tig + 4];
            }
#pragma unroll
            for (int tm = 0; tm < 4; tm++)
#pragma unroll
                for (int tn = 0; tn < 4; tn++)
                    mma_tf32(acc[tm][tn], a[tm], b[tn]);
        }
        __syncthreads();
    }

#pragma unroll
    for (int tm = 0; tm < 4; tm++) {
#pragma unroll
        for (int tn = 0; tn < 4; tn++) {
            int j = n0 + wn + tn * 8 + tig * 2;
            float bj0 = bias[j], bj1 = bias[j + 1];
#pragma unroll
            for (int half = 0; half < 2; half++) {
                int m = m0 + wm + tm * 16 + grp + half * 8;
                *(float2*)&Out[(size_t)m * DMODEL + j] =
                    make_float2(acc[tm][tn][half * 2 + 0] + bj0,
                                acc[tm][tn][half * 2 + 1] + bj1);
            }
        }
    }
}

extern "C" void kernel_launch(void* const* d_in, const int* in_sizes, int n_in,
                              void* d_out, int out_size)
{
    const float* q       = (const float*)d_in[0];
    const float* k       = (const float*)d_in[1];
    const float* v       = (const float*)d_in[2];
    const float* pos_emb = (const float*)d_in[3];
    const int*   mask    = (const int*)d_in[4];   // bool -> int32 in harness
    const float* Wq   = (const float*)d_in[5];
    const float* bq   = (const float*)d_in[6];
    const float* Wk   = (const float*)d_in[7];
    const float* bk   = (const float*)d_in[8];
    const float* Wv   = (const float*)d_in[9];
    const float* bv   = (const float*)d_in[10];
    const float* Wpos = (const float*)d_in[11];
    const float* Wout = (const float*)d_in[12];
    const float* bout = (const float*)d_in[13];
    const float* u      = (const float*)d_in[14];
    const float* v_bias = (const float*)d_in[15];

    float* out = (float*)d_out;
    float* out_ctx  = out;                                  // [8,1024,512]
    float* out_attn = out + (size_t)BATCH * SEQ * DMODEL;   // [8,8,1024,1024]

    static float *p_qu = nullptr, *p_qvb, *p_kh, *p_vh, *p_ph, *p_ctx, *p_pos, *p_psum;
    static uint32_t* p_mbits;
    if (!p_qu) {
        cudaGetSymbolAddress((void**)&p_qu,  g_qu);
        cudaGetSymbolAddress((void**)&p_qvb, g_qvb);
        cudaGetSymbolAddress((void**)&p_kh,  g_kh);
        cudaGetSymbolAddress((void**)&p_vh,  g_vh);
        cudaGetSymbolAddress((void**)&p_ph,  g_ph);
        cudaGetSymbolAddress((void**)&p_ctx, g_ctx);
        cudaGetSymbolAddress((void**)&p_pos, g_pos);
        cudaGetSymbolAddress((void**)&p_psum, g_psum);
        cudaGetSymbolAddress((void**)&p_mbits, g_mbits);
        cudaFuncSetAttribute(k_proj_tc,      cudaFuncAttributeMaxDynamicSharedMemorySize, TC_SMEM_BYTES);
        cudaFuncSetAttribute(k_pos_tc,       cudaFuncAttributeMaxDynamicSharedMemorySize, TC_SMEM_BYTES);
        cudaFuncSetAttribute(k_scores_fused, cudaFuncAttributeMaxDynamicSharedMemorySize, TC_SMEM_BYTES);
        cudaFuncSetAttribute(k_av_tc,        cudaFuncAttributeMaxDynamicSharedMemorySize, AV_SMEM_BYTES);
        cudaFuncSetAttribute(k_out_tc,       cudaFuncAttributeMaxDynamicSharedMemorySize, TC_SMEM_BYTES);
    }

    // mask bitpack (independent of projections)
    k_maskpack<<<1024, 256>>>(mask, p_mbits);

    // tf32 tensor projections
    dim3 gptc(DMODEL / 128, (BATCH * SEQ) / 128);   // (4, 64)
    k_proj_tc<<<gptc, 256, TC_SMEM_BYTES>>>(q,       Wq,   bq, p_qu, u, p_qvb, v_bias);
    k_proj_tc<<<gptc, 256, TC_SMEM_BYTES>>>(k,       Wk,   bk, p_kh, nullptr, nullptr, nullptr);
    k_proj_tc<<<gptc, 256, TC_SMEM_BYTES>>>(pos_emb, Wpos, nullptr, p_ph, nullptr, nullptr, nullptr);
    k_proj_tc<<<gptc, 256, TC_SMEM_BYTES>>>(v,       Wv,   bv, p_vh, nullptr, nullptr, nullptr);

    // pos scores -> scratch
    dim3 gs(SEQ / 128, SEQ / 128, BATCH * NHEAD);   // (8, 8, 64)
    k_pos_tc<<<gs, 256, TC_SMEM_BYTES>>>(p_qvb, p_ph, p_pos);

    // fused content GEMM + shift + mask + exp + row partials
    k_scores_fused<<<gs, 256, TC_SMEM_BYTES>>>(p_qu, p_kh, p_pos, p_mbits,
                                               out_attn, p_psum);

    // pipelined AV on exp-attn; normalizes attn in place + scales ctx
    dim3 ga(1, SEQ / 64, BATCH * NHEAD);            // (1, 16, 64)
    k_av_tc<<<ga, 256, AV_SMEM_BYTES>>>(out_attn, out_attn, p_vh, p_psum, p_ctx);

    // tf32 output projection
    dim3 go(DMODEL / 128, (BATCH * SEQ) / 128);     // (4, 64)
    k_out_tc<<<go, 256, TC_SMEM_BYTES>>>(p_ctx, Wout, bout, out_ctx);
}

// round 14
// speedup vs baseline: 1.4064x; 1.4060x over previous
#include <cuda_runtime.h>
#include <cstdint>

#define BATCH 8
#define SEQ   1024
#define DMODEL 512
#define NHEAD 8
#define HDIM  64

#define TCPAD 68
#define TC_SMEM_BYTES (2 * 128 * TCPAD * 4)

// pipelined AV kernel
#define AVSTR_A 36
#define AVSTR_B 68
#define AV_A_WORDS (64 * AVSTR_A)
#define AV_B_WORDS (32 * AVSTR_B)
#define AV_STAGE   (AV_A_WORDS + AV_B_WORDS)
#define AV_SMEM_BYTES (2 * AV_STAGE * 4)

static __device__ float g_qu [(size_t)BATCH*NHEAD*SEQ*HDIM];
static __device__ float g_qvb[(size_t)BATCH*NHEAD*SEQ*HDIM];
static __device__ float g_kh [(size_t)BATCH*NHEAD*SEQ*HDIM];
static __device__ float g_vh [(size_t)BATCH*NHEAD*SEQ*HDIM];
static __device__ float g_ph [(size_t)BATCH*NHEAD*SEQ*HDIM];
static __device__ float g_ctx[(size_t)BATCH*SEQ*DMODEL];
static __device__ float g_pos[(size_t)BATCH*NHEAD*SEQ*SEQ];
static __device__ uint32_t g_mbits[(size_t)BATCH*SEQ*(SEQ/32)];   // bitpacked mask

__device__ __forceinline__ uint32_t f2tf32(float x) {
    uint32_t t;
    asm("cvt.rna.tf32.f32 %0, %1;" : "=r"(t) : "f"(x));
    return t;
}

__device__ __forceinline__ void mma_tf32(float c[4], const uint32_t a[4], const uint32_t b[2]) {
    asm volatile(
        "mma.sync.aligned.m16n8k8.row.col.f32.tf32.tf32.f32 "
        "{%0,%1,%2,%3}, {%4,%5,%6,%7}, {%8,%9}, {%0,%1,%2,%3};"
        : "+f"(c[0]), "+f"(c[1]), "+f"(c[2]), "+f"(c[3])
        : "r"(a[0]), "r"(a[1]), "r"(a[2]), "r"(a[3]), "r"(b[0]), "r"(b[1]));
}

__device__ __forceinline__ void cp_async16(uint32_t saddr, const void* gptr) {
    asm volatile("cp.async.cg.shared.global [%0], [%1], 16;" :: "r"(saddr), "l"(gptr));
}
__device__ __forceinline__ void cp_commit() { asm volatile("cp.async.commit_group;"); }
template <int N>
__device__ __forceinline__ void cp_wait() { asm volatile("cp.async.wait_group %0;" :: "n"(N)); }

// ---------------------------------------------------------------------------
// Bitpack int32 mask -> 1 bit per element. 262144 words total.
// ---------------------------------------------------------------------------
__global__ __launch_bounds__(256)
void k_maskpack(const int* __restrict__ M, uint32_t* __restrict__ bits)
{
    const int lane = threadIdx.x & 31;
    const size_t gwarp = ((size_t)blockIdx.x * 256 + threadIdx.x) >> 5;  // 8192 warps
    const size_t nwarps = (size_t)gridDim.x * 8;
#pragma unroll
    for (int it = 0; it < 32; it++) {
        size_t w = gwarp + (size_t)it * nwarps;
        uint32_t bal = __ballot_sync(0xffffffffu, M[w * 32 + lane] != 0);
        if (lane == 0) bits[w] = bal;
    }
}

// ---------------------------------------------------------------------------
// TF32 NT projection GEMM: Y = X W^T (+ bias); head-major scatter; dual out opt.
// ---------------------------------------------------------------------------
__global__ __launch_bounds__(256)
void k_proj_tc(const float* __restrict__ X, const float* __restrict__ W,
               const float* __restrict__ bias,
               float* __restrict__ O1, const float* __restrict__ add1,
               float* __restrict__ O2, const float* __restrict__ add2)
{
    extern __shared__ uint32_t sm[];
    uint32_t* As = sm;
    uint32_t* Bs = sm + 128 * TCPAD;

    const int tid = threadIdx.x;
    const int m0 = blockIdx.y * 128;
    const int n0 = blockIdx.x * 128;
    const int lane = tid & 31, warp = tid >> 5;
    const int wm = (warp & 1) * 64, wn = (warp >> 1) * 32;
    const int grp = lane >> 2, tig = lane & 3;

    const int lrow  = tid >> 4;
    const int lcol4 = (tid & 15) * 4;

    float acc[4][4][4] = {};

    for (int k0 = 0; k0 < DMODEL; k0 += 64) {
#pragma unroll
        for (int i = 0; i < 8; i++) {
            int r = lrow + i * 16;
            float4 a4 = *(const float4*)(X + (size_t)(m0 + r) * DMODEL + k0 + lcol4);
            float4 b4 = *(const float4*)(W + (size_t)(n0 + r) * DMODEL + k0 + lcol4);
            *(uint4*)&As[r * TCPAD + lcol4] =
                make_uint4(f2tf32(a4.x), f2tf32(a4.y), f2tf32(a4.z), f2tf32(a4.w));
            *(uint4*)&Bs[r * TCPAD + lcol4] =
                make_uint4(f2tf32(b4.x), f2tf32(b4.y), f2tf32(b4.z), f2tf32(b4.w));
        }
        __syncthreads();

#pragma unroll
        for (int ks = 0; ks < 8; ks++) {
            const int kk = ks * 8;
            uint32_t a[4][4], b[4][2];
#pragma unroll
            for (int tm = 0; tm < 4; tm++) {
                int r = wm + tm * 16 + grp;
                a[tm][0] = As[r * TCPAD + kk + tig];
                a[tm][1] = As[(r + 8) * TCPAD + kk + tig];
                a[tm][2] = As[r * TCPAD + kk + tig + 4];
                a[tm][3] = As[(r + 8) * TCPAD + kk + tig + 4];
            }
#pragma unroll
            for (int tn = 0; tn < 4; tn++) {
                int c = wn + tn * 8 + grp;
                b[tn][0] = Bs[c * TCPAD + kk + tig];
                b[tn][1] = Bs[c * TCPAD + kk + tig + 4];
            }
#pragma unroll
            for (int tm = 0; tm < 4; tm++)
#pragma unroll
                for (int tn = 0; tn < 4; tn++)
                    mma_tf32(acc[tm][tn], a[tm], b[tn]);
        }
        __syncthreads();
    }

#pragma unroll
    for (int tm = 0; tm < 4; tm++) {
#pragma unroll
        for (int tn = 0; tn < 4; tn++) {
            int j = n0 + wn + tn * 8 + tig * 2;
            int hn = j >> 6, hd = j & (HDIM - 1);
            float bj0 = bias ? bias[j] : 0.0f;
            float bj1 = bias ? bias[j + 1] : 0.0f;
#pragma unroll
            for (int half = 0; half < 2; half++) {
                int m = m0 + wm + tm * 16 + grp + half * 8;
                int bb = m >> 10, s = m & (SEQ - 1);
                float v0 = acc[tm][tn][half * 2 + 0] + bj0;
                float v1 = acc[tm][tn][half * 2 + 1] + bj1;
                size_t off = (((size_t)bb * NHEAD + hn) * SEQ + s) * HDIM + hd;
                if (add1) {
                    *(float2*)&O1[off] = make_float2(v0 + add1[j], v1 + add1[j + 1]);
                } else {
                    *(float2*)&O1[off] = make_float2(v0, v1);
                }
                if (O2) {
                    *(float2*)&O2[off] = make_float2(v0 + add2[j], v1 + add2[j + 1]);
                }
            }
        }
    }
}

// ---------------------------------------------------------------------------
// TF32 batched score GEMM (NT, K=64): C[q,k] = sum_d A[q,d]*B[k,d]
// z in [0,64): content (qu x kh) -> C0 ; z in [64,128): pos (qvb x ph) -> C1
// ---------------------------------------------------------------------------
__global__ __launch_bounds__(256)
void k_scores_tc(const float* __restrict__ A0, const float* __restrict__ B0,
                 float* __restrict__ C0,
                 const float* __restrict__ A1, const float* __restrict__ B1,
                 float* __restrict__ C1)
{
    extern __shared__ uint32_t sm[];
    uint32_t* As = sm;
    uint32_t* Bs = sm + 128 * TCPAD;

    int z = blockIdx.z;
    const float *Aall, *Ball; float* Call;
    if (z < BATCH * NHEAD) { Aall = A0; Ball = B0; Call = C0; }
    else { z -= BATCH * NHEAD; Aall = A1; Ball = B1; Call = C1; }
    const float* X = Aall + (size_t)z * SEQ * HDIM;
    const float* W = Ball + (size_t)z * SEQ * HDIM;
    float* C = Call + (size_t)z * SEQ * SEQ;

    const int tid = threadIdx.x;
    const int m0 = blockIdx.y * 128;
    const int n0 = blockIdx.x * 128;
    const int lane = tid & 31, warp = tid >> 5;
    const int wm = (warp & 1) * 64, wn = (warp >> 1) * 32;
    const int grp = lane >> 2, tig = lane & 3;

    const int lrow  = tid >> 4;
    const int lcol4 = (tid & 15) * 4;

#pragma unroll
    for (int i = 0; i < 8; i++) {
        int r = lrow + i * 16;
        float4 a4 = *(const float4*)(X + (size_t)(m0 + r) * HDIM + lcol4);
        float4 b4 = *(const float4*)(W + (size_t)(n0 + r) * HDIM + lcol4);
        *(uint4*)&As[r * TCPAD + lcol4] =
            make_uint4(f2tf32(a4.x), f2tf32(a4.y), f2tf32(a4.z), f2tf32(a4.w));
        *(uint4*)&Bs[r * TCPAD + lcol4] =
            make_uint4(f2tf32(b4.x), f2tf32(b4.y), f2tf32(b4.z), f2tf32(b4.w));
    }
    __syncthreads();

    float acc[4][4][4] = {};
#pragma unroll
    for (int ks = 0; ks < 8; ks++) {
        const int kk = ks * 8;
        uint32_t a[4][4], b[4][2];
#pragma unroll
        for (int tm = 0; tm < 4; tm++) {
            int r = wm + tm * 16 + grp;
            a[tm][0] = As[r * TCPAD + kk + tig];
            a[tm][1] = As[(r + 8) * TCPAD + kk + tig];
            a[tm][2] = As[r * TCPAD + kk + tig + 4];
            a[tm][3] = As[(r + 8) * TCPAD + kk + tig + 4];
        }
#pragma unroll
        for (int tn = 0; tn < 4; tn++) {
            int c = wn + tn * 8 + grp;
            b[tn][0] = Bs[c * TCPAD + kk + tig];
            b[tn][1] = Bs[c * TCPAD + kk + tig + 4];
        }
#pragma unroll
        for (int tm = 0; tm < 4; tm++)
#pragma unroll
            for (int tn = 0; tn < 4; tn++)
                mma_tf32(acc[tm][tn], a[tm], b[tn]);
    }

#pragma unroll
    for (int tm = 0; tm < 4; tm++) {
#pragma unroll
        for (int tn = 0; tn < 4; tn++) {
            int col = n0 + wn + tn * 8 + tig * 2;
#pragma unroll
            for (int half = 0; half < 2; half++) {
                int row = m0 + wm + tm * 16 + grp + half * 8;
                *(float2*)&C[(size_t)row * SEQ + col] =
                    make_float2(acc[tm][tn][half * 2 + 0], acc[tm][tn][half * 2 + 1]);
            }
        }
    }
}

// ---------------------------------------------------------------------------
// Fused relative shift + scale + mask(bitpacked) + softmax. One block per row.
// shift[q,k] = pos[q, S-1-q+k] (k<=q); 0 (k==q+1); pos[q+1, k-q-2] (k>q+1)
// ---------------------------------------------------------------------------
__global__ __launch_bounds__(256)
void k_softmax(float* __restrict__ AttnOut, const float* __restrict__ Pos,
               const uint32_t* __restrict__ Mbits)
{
    const int row = blockIdx.x;
    const int q = row & (SEQ - 1);
    const int z = row >> 10;
    const int b = z >> 3;

    float* Crow = AttnOut + (size_t)row * SEQ;
    const float* P0 = Pos + ((size_t)z * SEQ + q) * SEQ;
    const float* P1 = P0 + SEQ;
    const uint32_t* mrow = Mbits + ((size_t)b * SEQ + q) * (SEQ / 32);

    const float scale = 0.04419417382415922f;  // 1/sqrt(512)
    const int tid = threadIdx.x;

    float vals[4];
    float lmax = -3.0e38f;
#pragma unroll
    for (int i = 0; i < 4; i++) {
        int k = tid + i * 256;
        float c = Crow[k];
        float p;
        if (k <= q)           p = P0[SEQ - 1 - q + k];
        else if (k == q + 1)  p = 0.0f;
        else                  p = P1[k - q - 2];
        float sc = (c + p) * scale;
        if ((mrow[k >> 5] >> (k & 31)) & 1u) sc = -10000.0f;
        vals[i] = sc;
        lmax = fmaxf(lmax, sc);
    }

    __shared__ float red[8];
#pragma unroll
    for (int o = 16; o; o >>= 1) lmax = fmaxf(lmax, __shfl_xor_sync(0xffffffffu, lmax, o));
    if ((tid & 31) == 0) red[tid >> 5] = lmax;
    __syncthreads();
    float bmax = red[0];
#pragma unroll
    for (int w = 1; w < 8; w++) bmax = fmaxf(bmax, red[w]);

    float lsum = 0.0f;
#pragma unroll
    for (int i = 0; i < 4; i++) {
        vals[i] = __expf(vals[i] - bmax);
        lsum += vals[i];
    }
#pragma unroll
    for (int o = 16; o; o >>= 1) lsum += __shfl_xor_sync(0xffffffffu, lsum, o);
    __syncthreads();
    if ((tid & 31) == 0) red[tid >> 5] = lsum;
    __syncthreads();
    float tot = 0.0f;
#pragma unroll
    for (int w = 0; w < 8; w++) tot += red[w];
    float inv = 1.0f / tot;

#pragma unroll
    for (int i = 0; i < 4; i++) {
        int k = tid + i * 256;
        Crow[k] = vals[i] * inv;
    }
}

// ---------------------------------------------------------------------------
// Pipelined TF32 batched AV GEMM (NN): Ctx[b][q][n*64+d] = sum_k attn*vh
// 64x64 block tile, K=1024 in 32-chunks, 2-stage cp.async double buffer.
// ---------------------------------------------------------------------------
__global__ __launch_bounds__(256)
void k_av_tc(const float* __restrict__ Attn, const float* __restrict__ Vall,
             float* __restrict__ Ctx)
{
    extern __shared__ float smf[];

    const int z = blockIdx.z;
    const int b = z >> 3, n = z & 7;
    const float* Ab = Attn + (size_t)z * SEQ * SEQ;
    const float* Bb = Vall + (size_t)z * SEQ * HDIM;

    const int tid = threadIdx.x;
    const int m0 = blockIdx.y * 64;
    const int lane = tid & 31, warp = tid >> 5;
    const int wm = (warp & 3) * 16, wn = (warp >> 2) * 32;
    const int grp = lane >> 2, tig = lane & 3;

    const int arow = tid >> 2, acol = (tid & 3) * 8;
    const int brow = tid >> 3, bcol = (tid & 7) * 8;

    const uint32_t s0 = (uint32_t)__cvta_generic_to_shared(smf);
    const uint32_t sA = s0 + (arow * AVSTR_A + acol) * 4;
    const uint32_t sB = s0 + (AV_A_WORDS + brow * AVSTR_B + bcol) * 4;
    const float* Agp = Ab + (size_t)(m0 + arow) * SEQ + acol;
    const float* Bgp = Bb + (size_t)brow * HDIM + bcol;

    float acc[4][4] = {};

    const int NK = SEQ / 32;

    cp_async16(sA,      Agp);
    cp_async16(sA + 16, Agp + 4);
    cp_async16(sB,      Bgp);
    cp_async16(sB + 16, Bgp + 4);
    cp_commit();

    for (int t = 0; t < NK; t++) {
        const int cur = t & 1;
        if (t + 1 < NK) {
            const uint32_t off = (uint32_t)((cur ^ 1) * AV_STAGE * 4);
            const int k0 = (t + 1) * 32;
            cp_async16(sA + off,      Agp + k0);
            cp_async16(sA + off + 16, Agp + k0 + 4);
            cp_async16(sB + off,      Bgp + (size_t)k0 * HDIM);
            cp_async16(sB + off + 16, Bgp + (size_t)k0 * HDIM + 4);
            cp_commit();
            cp_wait<1>();
        } else {
            cp_wait<0>();
        }
        __syncthreads();

        const float* As = smf + cur * AV_STAGE;
        const float* Bs = As + AV_A_WORDS;

#pragma unroll
        for (int ks = 0; ks < 4; ks++) {
            const int kk = ks * 8;
            uint32_t a[4], bfr[4][2];
            {
                int r = wm + grp;
                a[0] = f2tf32(As[r * AVSTR_A + kk + tig]);
                a[1] = f2tf32(As[(r + 8) * AVSTR_A + kk + tig]);
                a[2] = f2tf32(As[r * AVSTR_A + kk + tig + 4]);
                a[3] = f2tf32(As[(r + 8) * AVSTR_A + kk + tig + 4]);
            }
#pragma unroll
            for (int tn = 0; tn < 4; tn++) {
                int c = wn + tn * 8 + grp;
                bfr[tn][0] = f2tf32(Bs[(kk + tig) * AVSTR_B + c]);
                bfr[tn][1] = f2tf32(Bs[(kk + tig + 4) * AVSTR_B + c]);
            }
#pragma unroll
            for (int tn = 0; tn < 4; tn++)
                mma_tf32(acc[tn], a, bfr[tn]);
        }
        __syncthreads();
    }

#pragma unroll
    for (int tn = 0; tn < 4; tn++) {
        int d = wn + tn * 8 + tig * 2;
#pragma unroll
        for (int half = 0; half < 2; half++) {
            int qrow = m0 + wm + grp + half * 8;
            *(float2*)&Ctx[((size_t)b * SEQ + qrow) * DMODEL + n * HDIM + d] =
                make_float2(acc[tn][half * 2 + 0], acc[tn][half * 2 + 1]);
        }
    }
}

// ---------------------------------------------------------------------------
// TF32 output NT GEMM: Out[m,j] = sum_d Ctx[m,d]*Wout[j,d] + bout[j]
// ---------------------------------------------------------------------------
__global__ __launch_bounds__(256)
void k_out_tc(const float* __restrict__ X, const float* __restrict__ W,
              const float* __restrict__ bias, float* __restrict__ Out)
{
    extern __shared__ uint32_t sm[];
    uint32_t* As = sm;
    uint32_t* Bs = sm + 128 * TCPAD;

    const int tid = threadIdx.x;
    const int m0 = blockIdx.y * 128;
    const int n0 = blockIdx.x * 128;
    const int lane = tid & 31, warp = tid >> 5;
    const int wm = (warp & 1) * 64, wn = (warp >> 1) * 32;
    const int grp = lane >> 2, tig = lane & 3;

    const int lrow  = tid >> 4;
    const int lcol4 = (tid & 15) * 4;

    float acc[4][4][4] = {};

    for (int k0 = 0; k0 < DMODEL; k0 += 64) {
#pragma unroll
        for (int i = 0; i < 8; i++) {
            int r = lrow + i * 16;
            float4 a4 = *(const float4*)(X + (size_t)(m0 + r) * DMODEL + k0 + lcol4);
            float4 b4 = *(const float4*)(W + (size_t)(n0 + r) * DMODEL + k0 + lcol4);
            *(uint4*)&As[r * TCPAD + lcol4] =
                make_uint4(f2tf32(a4.x), f2tf32(a4.y), f2tf32(a4.z), f2tf32(a4.w));
            *(uint4*)&Bs[r * TCPAD + lcol4] =
                make_uint4(f2tf32(b4.x), f2tf32(b4.y), f2tf32(b4.z), f2tf32(b4.w));
        }
        __syncthreads();

#pragma unroll
        for (int ks = 0; ks < 8; ks++) {
            const int kk = ks * 8;
            uint32_t a[4][4], b[4][2];
#pragma unroll
            for (int tm = 0; tm < 4; tm++) {
                int r = wm + tm * 16 + grp;
                a[tm][0] = As[r * TCPAD + kk + tig];
                a[tm][1] = As[(r + 8) * TCPAD + kk + tig];
                a[tm][2] = As[r * TCPAD + kk + tig + 4];
                a[tm][3] = As[(r + 8) * TCPAD + kk + tig + 4];
            }
#pragma unroll
            for (int tn = 0; tn < 4; tn++) {
                int c = wn + tn * 8 + grp;
                b[tn][0] = Bs[c * TCPAD + kk + tig];
                b[tn][1] = Bs[c * TCPAD + kk + tig + 4];
            }
#pragma unroll
            for (int tm = 0; tm < 4; tm++)
#pragma unroll
                for (int tn = 0; tn < 4; tn++)
                    mma_tf32(acc[tm][tn], a[tm], b[tn]);
        }
        __syncthreads();
    }

#pragma unroll
    for (int tm = 0; tm < 4; tm++) {
#pragma unroll
        for (int tn = 0; tn < 4; tn++) {
            int j = n0 + wn + tn * 8 + tig * 2;
            float bj0 = bias[j], bj1 = bias[j + 1];
#pragma unroll
            for (int half = 0; half < 2; half++) {
                int m = m0 + wm + tm * 16 + grp + half * 8;
                *(float2*)&Out[(size_t)m * DMODEL + j] =
                    make_float2(acc[tm][tn][half * 2 + 0] + bj0,
                                acc[tm][tn][half * 2 + 1] + bj1);
            }
        }
    }
}

extern "C" void kernel_launch(void* const* d_in, const int* in_sizes, int n_in,
                              void* d_out, int out_size)
{
    const float* q       = (const float*)d_in[0];
    const float* k       = (const float*)d_in[1];
    const float* v       = (const float*)d_in[2];
    const float* pos_emb = (const float*)d_in[3];
    const int*   mask    = (const int*)d_in[4];   // bool -> int32 in harness
    const float* Wq   = (const float*)d_in[5];
    const float* bq   = (const float*)d_in[6];
    const float* Wk   = (const float*)d_in[7];
    const float* bk   = (const float*)d_in[8];
    const float* Wv   = (const float*)d_in[9];
    const float* bv   = (const float*)d_in[10];
    const float* Wpos = (const float*)d_in[11];
    const float* Wout = (const float*)d_in[12];
    const float* bout = (const float*)d_in[13];
    const float* u      = (const float*)d_in[14];
    const float* v_bias = (const float*)d_in[15];

    float* out = (float*)d_out;
    float* out_ctx  = out;                                  // [8,1024,512]
    float* out_attn = out + (size_t)BATCH * SEQ * DMODEL;   // [8,8,1024,1024]

    static float *p_qu = nullptr, *p_qvb, *p_kh, *p_vh, *p_ph, *p_ctx, *p_pos;
    static uint32_t* p_mbits;
    if (!p_qu) {
        cudaGetSymbolAddress((void**)&p_qu,  g_qu);
        cudaGetSymbolAddress((void**)&p_qvb, g_qvb);
        cudaGetSymbolAddress((void**)&p_kh,  g_kh);
        cudaGetSymbolAddress((void**)&p_vh,  g_vh);
        cudaGetSymbolAddress((void**)&p_ph,  g_ph);
        cudaGetSymbolAddress((void**)&p_ctx, g_ctx);
        cudaGetSymbolAddress((void**)&p_pos, g_pos);
        cudaGetSymbolAddress((void**)&p_mbits, g_mbits);
        cudaFuncSetAttribute(k_proj_tc,   cudaFuncAttributeMaxDynamicSharedMemorySize, TC_SMEM_BYTES);
        cudaFuncSetAttribute(k_scores_tc, cudaFuncAttributeMaxDynamicSharedMemorySize, TC_SMEM_BYTES);
        cudaFuncSetAttribute(k_av_tc,     cudaFuncAttributeMaxDynamicSharedMemorySize, AV_SMEM_BYTES);
        cudaFuncSetAttribute(k_out_tc,    cudaFuncAttributeMaxDynamicSharedMemorySize, TC_SMEM_BYTES);
    }

    // mask bitpack (off critical path; overlaps nothing heavy)
    k_maskpack<<<1024, 256>>>(mask, p_mbits);

    // tf32 tensor projections (Round-6/8 proven path)
    dim3 gptc(DMODEL / 128, (BATCH * SEQ) / 128);   // (4, 64)
    k_proj_tc<<<gptc, 256, TC_SMEM_BYTES>>>(q,       Wq,   bq, p_qu, u, p_qvb, v_bias);
    k_proj_tc<<<gptc, 256, TC_SMEM_BYTES>>>(k,       Wk,   bk, p_kh, nullptr, nullptr, nullptr);
    k_proj_tc<<<gptc, 256, TC_SMEM_BYTES>>>(pos_emb, Wpos, nullptr, p_ph, nullptr, nullptr, nullptr);
    k_proj_tc<<<gptc, 256, TC_SMEM_BYTES>>>(v,       Wv,   bv, p_vh, nullptr, nullptr, nullptr);

    // tf32 tensor score GEMMs (content + pos in one launch)
    dim3 gs(SEQ / 128, SEQ / 128, 2 * BATCH * NHEAD); // (8, 8, 128)
    k_scores_tc<<<gs, 256, TC_SMEM_BYTES>>>(p_qu,  p_kh, out_attn,
                                            p_qvb, p_ph, p_pos);

    // softmax with bitpacked mask
    k_softmax<<<BATCH * NHEAD * SEQ, 256>>>(out_attn, p_pos, p_mbits);

    // pipelined tf32 tensor AV
    dim3 ga(1, SEQ / 64, BATCH * NHEAD);              // (1, 16, 64)
    k_av_tc<<<ga, 256, AV_SMEM_BYTES>>>(out_attn, p_vh, p_ctx);

    // tf32 tensor output projection
    dim3 go(DMODEL / 128, (BATCH * SEQ) / 128);       // (4, 64)
    k_out_tc<<<go, 256, TC_SMEM_BYTES>>>(p_ctx, Wout, bout, out_ctx);
}